// round 15
// baseline (speedup 1.0000x reference)
#include <cuda_runtime.h>
#include <cuda_fp16.h>
#include <cstdint>

#define S_LEN 2048
#define NB 2
#define NH 16
#define DK 64
#define DM 1024
#define MROWS (NB * S_LEN)   // 4096
#define HEADELEMS ((size_t)NB * NH * S_LEN * DK)

// ---------------- scratch (__device__ globals; no allocs allowed) ----------
__device__ __half g_q[HEADELEMS];                        // [b,h][t][d], 1/8 folded
__device__ __half g_k[HEADELEMS];                        // [b,h][t][d]
__device__ __half g_vt[HEADELEMS];                       // [b,h][d][t]
__device__ __half g_at[(size_t)MROWS * DM];              // attention out [b][s][h*64+d]
__device__ __half g_wq[DM * DM], g_wk[DM * DM], g_wv[DM * DM], g_wo[DM * DM];

// ---------------- PTX helpers ----------------------------------------------
__device__ __forceinline__ uint32_t smem_u32(const void* p) {
    uint32_t a;
    asm("{ .reg .u64 t; cvta.to.shared.u64 t, %1; cvt.u32.u64 %0, t; }" : "=r"(a) : "l"(p));
    return a;
}
// L2-only (cg): every tile is stream-once; keep L1 for ldmatrix traffic.
#define CP16(dst, src) asm volatile("cp.async.cg.shared.global [%0], [%1], 16;" :: "r"(dst), "l"(src))
#define CPCOMMIT()     asm volatile("cp.async.commit_group;" ::: "memory")
#define CPWAIT0()      asm volatile("cp.async.wait_group 0;" ::: "memory")

__device__ __forceinline__ void ldsm4(uint32_t* r, uint32_t a) {
    asm volatile("ldmatrix.sync.aligned.m8n8.x4.shared.b16 {%0,%1,%2,%3}, [%4];"
                 : "=r"(r[0]), "=r"(r[1]), "=r"(r[2]), "=r"(r[3]) : "r"(a));
}
__device__ __forceinline__ void mma16816(float* d, const uint32_t* a, const uint32_t* b) {
    asm volatile("mma.sync.aligned.m16n8k16.row.col.f32.f16.f16.f32 "
                 "{%0,%1,%2,%3},{%4,%5,%6,%7},{%8,%9},{%0,%1,%2,%3};"
                 : "+f"(d[0]), "+f"(d[1]), "+f"(d[2]), "+f"(d[3])
                 : "r"(a[0]), "r"(a[1]), "r"(a[2]), "r"(a[3]), "r"(b[0]), "r"(b[1]));
}

__device__ __forceinline__ uint32_t pack2(uint16_t a, uint16_t b) {
    return (uint32_t)a | ((uint32_t)b << 16);
}
__device__ __forceinline__ uint32_t pcvt2(float x, float y) {
    return pack2(__half_as_ushort(__float2half_rn(x)),
                 __half_as_ushort(__float2half_rn(y)));
}

// ---------------------------------------------------------------------------
// Fused weight transpose + convert (z selects which W):  T[n][k] = fp16(W[k][n])
// ---------------------------------------------------------------------------
__global__ __launch_bounds__(256) void wsplit_kernel(
    const float* __restrict__ W0, const float* __restrict__ W1,
    const float* __restrict__ W2, const float* __restrict__ W3,
    __half* __restrict__ T0, __half* __restrict__ T1,
    __half* __restrict__ T2, __half* __restrict__ T3)
{
    const int z = blockIdx.z;
    const float* W = (z == 0) ? W0 : (z == 1) ? W1 : (z == 2) ? W2 : W3;
    __half* Th     = (z == 0) ? T0 : (z == 1) ? T1 : (z == 2) ? T2 : T3;

    __shared__ float ts[32][33];
    const int tid = threadIdx.x;
    const int tx = tid & 31, ty = tid >> 5;
    const int k0 = blockIdx.x * 32, n0 = blockIdx.y * 32;
#pragma unroll
    for (int p = 0; p < 4; p++)
        ts[ty + 8 * p][tx] = W[(size_t)(k0 + ty + 8 * p) * DM + n0 + tx];
    __syncthreads();
#pragma unroll
    for (int p = 0; p < 4; p++) {
        const int r = ty + 8 * p;
        Th[(size_t)(n0 + r) * DM + k0 + tx] = __float2half_rn(ts[tx][r]);
    }
}

// ---------------------------------------------------------------------------
// Fused QKV GEMM: K macro-chunk 64 (4 k16 steps per sync), 144B-stride stages.
// A (fp32) staged in two 32-col register halves per macro-chunk.
// ---------------------------------------------------------------------------
#define Q_ST 18432              // stage: 128 rows x 144B
#define G_SMEM (4 * Q_ST)       // 73728 (also >= 128*136*2 V-bounce)
#define TPAD 136

__global__ __launch_bounds__(256, 2) void gemm_qkv_kernel(
    const float* __restrict__ A0, const float* __restrict__ A1,
    const float* __restrict__ A2,
    const __half* __restrict__ B0, const __half* __restrict__ B1,
    const __half* __restrict__ B2,
    const float* __restrict__ bias0, const float* __restrict__ bias1,
    const float* __restrict__ bias2,
    __half* __restrict__ O0, __half* __restrict__ O1, __half* __restrict__ O2)
{
    extern __shared__ char smc[];
    const uint32_t smb = smem_u32(smc);
    const int z = blockIdx.z;
    const float*  A    = (z == 0) ? A0 : (z == 1) ? A1 : A2;
    const __half* Bh   = (z == 0) ? B0 : (z == 1) ? B1 : B2;
    const float*  bias = (z == 0) ? bias0 : (z == 1) ? bias1 : bias2;
    __half* Oh         = (z == 0) ? O0 : (z == 1) ? O1 : O2;

    const int tid = threadIdx.x, lane = tid & 31, wid = tid >> 5;
    const int m0 = blockIdx.y * 128, n0 = blockIdx.x * 128;
    const int wm = (wid >> 2) * 64, wn = (wid & 3) * 32;
    const uint32_t SAH = smb, SBH = smb + 2 * Q_ST;

    const int r0a = tid >> 2, c0a = tid & 3;   // A loader: 64 rows x 4x8 fp32 cols

    // prologue: A chunk0 half0 -> regs; B chunk0 (64 k-cols) -> cp.async
    float4 areg[2][2];
#pragma unroll
    for (int p = 0; p < 2; p++) {
        const float* src = A + (size_t)(m0 + r0a + p * 64) * DM + c0a * 8;
        areg[p][0] = ((const float4*)src)[0];
        areg[p][1] = ((const float4*)src)[1];
    }
#pragma unroll
    for (int p = 0; p < 4; p++) {
        const int idx = tid + p * 256, r = idx >> 3, c = idx & 7;
        CP16(SBH + (uint32_t)r * 144u + (uint32_t)c * 16u,
             Bh + (size_t)(n0 + r) * DM + c * 8);
    }
    CPCOMMIT();

    float acc[4][4][4];
#pragma unroll
    for (int a = 0; a < 4; a++)
#pragma unroll
        for (int b = 0; b < 4; b++)
#pragma unroll
            for (int c = 0; c < 4; c++) acc[a][b][c] = 0.f;

    for (int ch = 0; ch < 16; ch++) {
        const uint32_t so = (uint32_t)(ch & 1) * Q_ST;
        // store A half0 (cols 0-31 of this macro-chunk)
#pragma unroll
        for (int p = 0; p < 2; p++) {
            uint4 v;
            v.x = pcvt2(areg[p][0].x, areg[p][0].y);
            v.y = pcvt2(areg[p][0].z, areg[p][0].w);
            v.z = pcvt2(areg[p][1].x, areg[p][1].y);
            v.w = pcvt2(areg[p][1].z, areg[p][1].w);
            *(uint4*)(smc + (uint32_t)(r0a + p * 64) * 144u +
                      (uint32_t)c0a * 16u + so) = v;
        }
        // load + store A half1 (cols 32-63)
        {
            const int k0 = ch * 64 + 32;
#pragma unroll
            for (int p = 0; p < 2; p++) {
                const float* src = A + (size_t)(m0 + r0a + p * 64) * DM + k0 + c0a * 8;
                areg[p][0] = ((const float4*)src)[0];
                areg[p][1] = ((const float4*)src)[1];
            }
#pragma unroll
            for (int p = 0; p < 2; p++) {
                uint4 v;
                v.x = pcvt2(areg[p][0].x, areg[p][0].y);
                v.y = pcvt2(areg[p][0].z, areg[p][0].w);
                v.z = pcvt2(areg[p][1].x, areg[p][1].y);
                v.w = pcvt2(areg[p][1].z, areg[p][1].w);
                *(uint4*)(smc + (uint32_t)(r0a + p * 64) * 144u + 64u +
                          (uint32_t)c0a * 16u + so) = v;
            }
        }
        CPWAIT0();
        __syncthreads();
        if (ch + 1 < 16) {
            const int k0 = (ch + 1) * 64;
            const uint32_t sn = (uint32_t)((ch + 1) & 1) * Q_ST;
#pragma unroll
            for (int p = 0; p < 4; p++) {
                const int idx = tid + p * 256, r = idx >> 3, c = idx & 7;
                CP16(SBH + (uint32_t)r * 144u + (uint32_t)c * 16u + sn,
                     Bh + (size_t)(n0 + r) * DM + k0 + c * 8);
            }
            CPCOMMIT();
#pragma unroll
            for (int p = 0; p < 2; p++) {
                const float* src = A + (size_t)(m0 + r0a + p * 64) * DM + k0 + c0a * 8;
                areg[p][0] = ((const float4*)src)[0];
                areg[p][1] = ((const float4*)src)[1];
            }
        }
#pragma unroll
        for (int ks = 0; ks < 4; ks++) {
            uint32_t ah[4][4], bh[4][2];
            const uint32_t aoff = (uint32_t)((lane & 15) * 144 +
                                  (ks * 16 + (lane >> 4) * 8) * 2) + so;
#pragma unroll
            for (int mb = 0; mb < 4; mb++)
                ldsm4(ah[mb], SAH + (uint32_t)(wm + mb * 16) * 144u + aoff);
            const uint32_t boff = (uint32_t)(((lane >> 4) & 1) * 8 * 144 +
                                  (lane & 7) * 144 +
                                  (ks * 16 + ((lane >> 3) & 1) * 8) * 2) + so;
#pragma unroll
            for (int nbp = 0; nbp < 2; nbp++) {
                uint32_t t[4];
                ldsm4(t, SBH + (uint32_t)(wn + nbp * 16) * 144u + boff);
                bh[2 * nbp][0] = t[0];     bh[2 * nbp][1] = t[1];
                bh[2 * nbp + 1][0] = t[2]; bh[2 * nbp + 1][1] = t[3];
            }
#pragma unroll
            for (int mb = 0; mb < 4; mb++)
#pragma unroll
                for (int nb = 0; nb < 4; nb++)
                    mma16816(acc[mb][nb], ah[mb], bh[nb]);
        }
    }
    __syncthreads();

    const int lr = lane >> 2, lc = (lane & 3) * 2;
    if (z != 2) {
        const float sc = (z == 0) ? 0.125f : 1.0f;
#pragma unroll
        for (int mb = 0; mb < 4; mb++) {
#pragma unroll
            for (int nb = 0; nb < 4; nb++) {
                const int col = n0 + wn + nb * 8 + lc;
                const float b0 = bias[col], b1 = bias[col + 1];
#pragma unroll
                for (int half_ = 0; half_ < 2; half_++) {
                    const int row = m0 + wm + mb * 16 + lr + 8 * half_;
                    const float v0 = (acc[mb][nb][2 * half_] + b0) * sc;
                    const float v1 = (acc[mb][nb][2 * half_ + 1] + b1) * sc;
                    const int bb = row >> 11, ss = row & (S_LEN - 1);
                    const int h = col >> 6, d = col & 63;
                    const size_t base = (((size_t)(bb * NH + h) * S_LEN + ss) << 6) + d;
                    *(uint32_t*)(Oh + base) = pcvt2(v0, v1);
                }
            }
        }
    } else {
        __half* tsm = (__half*)smc;
#pragma unroll
        for (int mb = 0; mb < 4; mb++) {
#pragma unroll
            for (int nb = 0; nb < 4; nb++) {
                const int col = wn + nb * 8 + lc;
                const float b0 = bias[n0 + col], b1 = bias[n0 + col + 1];
#pragma unroll
                for (int half_ = 0; half_ < 2; half_++) {
                    const int row = wm + mb * 16 + lr + 8 * half_;
                    tsm[(size_t)col * TPAD + row] =
                        __float2half_rn(acc[mb][nb][2 * half_] + b0);
                    tsm[(size_t)(col + 1) * TPAD + row] =
                        __float2half_rn(acc[mb][nb][2 * half_ + 1] + b1);
                }
            }
        }
        __syncthreads();
        const int dl = tid >> 1;
        const int tof = (tid & 1) * 64;
        const int bb = m0 >> 11, ss0 = (m0 & (S_LEN - 1)) + tof;
        const int n = n0 + dl, h = n >> 6, d = n & 63;
        __half* dst = Oh + ((size_t)(bb * NH + h) * DK + d) * S_LEN + ss0;
        const __half* srcr = tsm + (size_t)dl * TPAD + tof;
#pragma unroll
        for (int j = 0; j < 8; j++)
            ((uint4*)dst)[j] = ((const uint4*)srcr)[j];
    }
}

// ---------------------------------------------------------------------------
// Output projection GEMM: macro-chunk 64, 144B rows.
// ---------------------------------------------------------------------------
#define O_ST 18432
#define O_SMEM (4 * O_ST)

__global__ __launch_bounds__(256, 2) void gemm_o_kernel(
    const __half* __restrict__ Ah, const __half* __restrict__ Bh,
    const float* __restrict__ bias, float* __restrict__ Of)
{
    extern __shared__ char smc[];
    const uint32_t smb = smem_u32(smc);
    const int tid = threadIdx.x, lane = tid & 31, wid = tid >> 5;
    const int m0 = blockIdx.y * 128, n0 = blockIdx.x * 128;
    const int wm = (wid >> 2) * 64, wn = (wid & 3) * 32;
    const uint32_t SAH = smb, SBH = smb + 2 * O_ST;

#pragma unroll
    for (int p = 0; p < 4; p++) {
        const int idx = tid + p * 256, r = idx >> 3, c = idx & 7;
        const uint32_t d = (uint32_t)r * 144u + (uint32_t)c * 16u;
        CP16(SAH + d, Ah + (size_t)(m0 + r) * DM + c * 8);
        CP16(SBH + d, Bh + (size_t)(n0 + r) * DM + c * 8);
    }
    CPCOMMIT();

    float acc[4][4][4];
#pragma unroll
    for (int a = 0; a < 4; a++)
#pragma unroll
        for (int b = 0; b < 4; b++)
#pragma unroll
            for (int c = 0; c < 4; c++) acc[a][b][c] = 0.f;

    CPWAIT0();
    __syncthreads();

    for (int ch = 0; ch < 16; ch++) {
        if (ch > 0) { CPWAIT0(); __syncthreads(); }
        if (ch + 1 < 16) {
            const int k0 = (ch + 1) * 64;
            const uint32_t sn = (uint32_t)((ch + 1) & 1) * O_ST;
#pragma unroll
            for (int p = 0; p < 4; p++) {
                const int idx = tid + p * 256, r = idx >> 3, c = idx & 7;
                const uint32_t d = (uint32_t)r * 144u + (uint32_t)c * 16u + sn;
                CP16(SAH + d, Ah + (size_t)(m0 + r) * DM + k0 + c * 8);
                CP16(SBH + d, Bh + (size_t)(n0 + r) * DM + k0 + c * 8);
            }
            CPCOMMIT();
        }
        const uint32_t so = (uint32_t)(ch & 1) * O_ST;
#pragma unroll
        for (int ks = 0; ks < 4; ks++) {
            uint32_t ah[4][4], bh[4][2];
            const uint32_t aoff = (uint32_t)((lane & 15) * 144 +
                                  (ks * 16 + (lane >> 4) * 8) * 2) + so;
#pragma unroll
            for (int mb = 0; mb < 4; mb++)
                ldsm4(ah[mb], SAH + (uint32_t)(wm + mb * 16) * 144u + aoff);
            const uint32_t boff = (uint32_t)(((lane >> 4) & 1) * 8 * 144 +
                                  (lane & 7) * 144 +
                                  (ks * 16 + ((lane >> 3) & 1) * 8) * 2) + so;
#pragma unroll
            for (int nbp = 0; nbp < 2; nbp++) {
                uint32_t t[4];
                ldsm4(t, SBH + (uint32_t)(wn + nbp * 16) * 144u + boff);
                bh[2 * nbp][0] = t[0];     bh[2 * nbp][1] = t[1];
                bh[2 * nbp + 1][0] = t[2]; bh[2 * nbp + 1][1] = t[3];
            }
#pragma unroll
            for (int mb = 0; mb < 4; mb++)
#pragma unroll
                for (int nb = 0; nb < 4; nb++)
                    mma16816(acc[mb][nb], ah[mb], bh[nb]);
        }
    }

    const int lr = lane >> 2, lc = (lane & 3) * 2;
#pragma unroll
    for (int mb = 0; mb < 4; mb++) {
#pragma unroll
        for (int nb = 0; nb < 4; nb++) {
            const int col = n0 + wn + nb * 8 + lc;
            const float b0 = bias[col], b1 = bias[col + 1];
#pragma unroll
            for (int half_ = 0; half_ < 2; half_++) {
                const int row = m0 + wm + mb * 16 + lr + 8 * half_;
                *(float2*)(Of + (size_t)row * DM + col) =
                    make_float2(acc[mb][nb][2 * half_] + b0,
                                acc[mb][nb][2 * half_ + 1] + b1);
            }
        }
    }
}

// ---------------------------------------------------------------------------
// Flash attention: KV macro-chunk 128, Q frags hoisted.
// ---------------------------------------------------------------------------
#define AK_ST 18432
#define AV_ST 17408
#define A_QB  18432
#define A_SMEM (A_QB + 2 * AK_ST + 2 * AV_ST)

__global__ __launch_bounds__(256, 2) void attn_mma_kernel(
    const __half* __restrict__ Qh, const __half* __restrict__ Kh,
    const __half* __restrict__ Vth, __half* __restrict__ AO)
{
    extern __shared__ char smc[];
    const uint32_t smb = smem_u32(smc);
    const int tid = threadIdx.x, lane = tid & 31, wid = tid >> 5;
    const int bh = blockIdx.y;
    const int q0 = blockIdx.x * 128;
    const uint32_t SQH = smb;
    const uint32_t SKH = smb + A_QB, SVH = SKH + 2 * AK_ST;

    const size_t qbase = ((size_t)bh * S_LEN + q0) * DK;
    const size_t kbase = (size_t)bh * S_LEN * DK;
    const size_t vbase = (size_t)bh * DK * S_LEN;

    {
#pragma unroll
        for (int p = 0; p < 4; p++) {
            const int idx = tid + p * 256, r = idx >> 3, c = idx & 7;
            CP16(SQH + (uint32_t)r * 144u + (uint32_t)c * 16u,
                 Qh + qbase + (size_t)r * DK + c * 8);
            CP16(SKH + (uint32_t)r * 144u + (uint32_t)c * 16u,
                 Kh + kbase + (size_t)r * DK + c * 8);
        }
#pragma unroll
        for (int p = 0; p < 4; p++) {
            const int idx = tid + p * 256, r = idx >> 4, c = idx & 15;
            CP16(SVH + (uint32_t)r * 272u + (uint32_t)c * 16u,
                 Vth + vbase + (size_t)r * S_LEN + c * 8);
        }
        CPCOMMIT();
    }

    const int r0 = wid * 16;
    float oacc[8][4];
    float lsum[2] = {0.f, 0.f};
#pragma unroll
    for (int db = 0; db < 8; db++)
#pragma unroll
        for (int e = 0; e < 4; e++) oacc[db][e] = 0.f;

    CPWAIT0();
    __syncthreads();

    uint32_t qf_all[4][4];
#pragma unroll
    for (int ks = 0; ks < 4; ks++)
        ldsm4(qf_all[ks], SQH + (uint32_t)((r0 + (lane & 15)) * 144 +
                                           (ks * 16 + (lane >> 4) * 8) * 2));

    for (int i = 0; i < 16; i++) {
        if (i > 0) { CPWAIT0(); __syncthreads(); }
        if (i + 1 < 16) {
            const int t0 = (i + 1) * 128;
            const uint32_t skn = (uint32_t)((i + 1) & 1) * AK_ST;
            const uint32_t svn = (uint32_t)((i + 1) & 1) * AV_ST;
#pragma unroll
            for (int p = 0; p < 4; p++) {
                const int idx = tid + p * 256, r = idx >> 3, c = idx & 7;
                CP16(SKH + (uint32_t)r * 144u + (uint32_t)c * 16u + skn,
                     Kh + kbase + (size_t)(t0 + r) * DK + c * 8);
            }
#pragma unroll
            for (int p = 0; p < 4; p++) {
                const int idx = tid + p * 256, r = idx >> 4, c = idx & 15;
                CP16(SVH + (uint32_t)r * 272u + (uint32_t)c * 16u + svn,
                     Vth + vbase + (size_t)r * S_LEN + t0 + c * 8);
            }
            CPCOMMIT();
        }
        const uint32_t sk = (uint32_t)(i & 1) * AK_ST;
        const uint32_t sv = (uint32_t)(i & 1) * AV_ST;

#pragma unroll
        for (int hf = 0; hf < 2; hf++) {
            float sacc[8][4];
#pragma unroll
            for (int nb = 0; nb < 8; nb++)
#pragma unroll
                for (int e = 0; e < 4; e++) sacc[nb][e] = 0.f;
            const uint32_t kbs = SKH + sk + (uint32_t)(hf * 64) * 144u;
#pragma unroll
            for (int ks = 0; ks < 4; ks++) {
                const uint32_t bo = (uint32_t)(((lane >> 4) & 1) * 8 * 144 +
                                     (lane & 7) * 144 +
                                     (ks * 16 + ((lane >> 3) & 1) * 8) * 2);
#pragma unroll
                for (int nbp = 0; nbp < 4; nbp++) {
                    uint32_t t[4];
                    ldsm4(t, kbs + (uint32_t)(nbp * 16) * 144u + bo);
                    mma16816(sacc[2 * nbp],     qf_all[ks], t);
                    mma16816(sacc[2 * nbp + 1], qf_all[ks], t + 2);
                }
            }

#pragma unroll
            for (int nb = 0; nb < 8; nb++)
#pragma unroll
                for (int e = 0; e < 4; e++) {
                    const float p = __expf(sacc[nb][e]);
                    lsum[e >> 1] += p;
                    sacc[nb][e] = p;
                }

            const uint32_t vbs = SVH + sv;
#pragma unroll
            for (int ts = 0; ts < 4; ts++) {
                uint32_t ph[4];
                ph[0] = pcvt2(sacc[2 * ts][0],     sacc[2 * ts][1]);
                ph[1] = pcvt2(sacc[2 * ts][2],     sacc[2 * ts][3]);
                ph[2] = pcvt2(sacc[2 * ts + 1][0], sacc[2 * ts + 1][1]);
                ph[3] = pcvt2(sacc[2 * ts + 1][2], sacc[2 * ts + 1][3]);
                const uint32_t vo = (uint32_t)(((lane >> 4) & 1) * 8 * 272 +
                                     (lane & 7) * 272 +
                                     (hf * 64 + ts * 16 + ((lane >> 3) & 1) * 8) * 2);
#pragma unroll
                for (int dbp = 0; dbp < 4; dbp++) {
                    uint32_t t[4];
                    ldsm4(t, vbs + (uint32_t)(dbp * 16) * 272u + vo);
                    mma16816(oacc[2 * dbp],     ph, t);
                    mma16816(oacc[2 * dbp + 1], ph, t + 2);
                }
            }
        }
    }

#pragma unroll
    for (int e = 0; e < 2; e++) {
        lsum[e] += __shfl_xor_sync(0xffffffffu, lsum[e], 1);
        lsum[e] += __shfl_xor_sync(0xffffffffu, lsum[e], 2);
    }
    const float inv0 = 1.f / lsum[0], inv1 = 1.f / lsum[1];

    const int bb = bh >> 4, hh = bh & 15;
    const int rowa = q0 + r0 + (lane >> 2);
#pragma unroll
    for (int db = 0; db < 8; db++) {
        const int col = hh * 64 + db * 8 + (lane & 3) * 2;
        const size_t ba = ((size_t)bb * S_LEN + rowa) * DM + col;
        const size_t bb2 = ba + (size_t)8 * DM;
        *(uint32_t*)(AO + ba)  = pcvt2(oacc[db][0] * inv0, oacc[db][1] * inv0);
        *(uint32_t*)(AO + bb2) = pcvt2(oacc[db][2] * inv1, oacc[db][3] * inv1);
    }
}

// ---------------------------------------------------------------------------
extern "C" void kernel_launch(void* const* d_in, const int* in_sizes, int n_in,
                              void* d_out, int out_size)
{
    const float* q  = (const float*)d_in[0];
    const float* k  = (const float*)d_in[1];
    const float* v  = (const float*)d_in[2];
    const float* Wq = (const float*)d_in[3];
    const float* bq = (const float*)d_in[4];
    const float* Wk = (const float*)d_in[5];
    const float* bk = (const float*)d_in[6];
    const float* Wv = (const float*)d_in[7];
    const float* bv = (const float*)d_in[8];
    const float* Wo = (const float*)d_in[9];
    const float* bo = (const float*)d_in[10];
    float* out = (float*)d_out;

    __half *qh, *kh, *vt, *at, *wq, *wk, *wv, *wo;
    cudaGetSymbolAddress((void**)&qh, g_q);
    cudaGetSymbolAddress((void**)&kh, g_k);
    cudaGetSymbolAddress((void**)&vt, g_vt);
    cudaGetSymbolAddress((void**)&at, g_at);
    cudaGetSymbolAddress((void**)&wq, g_wq);
    cudaGetSymbolAddress((void**)&wk, g_wk);
    cudaGetSymbolAddress((void**)&wv, g_wv);
    cudaGetSymbolAddress((void**)&wo, g_wo);

    cudaFuncSetAttribute(gemm_qkv_kernel, cudaFuncAttributeMaxDynamicSharedMemorySize, G_SMEM);
    cudaFuncSetAttribute(gemm_o_kernel, cudaFuncAttributeMaxDynamicSharedMemorySize, O_SMEM);
    cudaFuncSetAttribute(attn_mma_kernel, cudaFuncAttributeMaxDynamicSharedMemorySize, A_SMEM);

    dim3 wg(32, 32, 4);
    wsplit_kernel<<<wg, 256>>>(Wq, Wk, Wv, Wo, wq, wk, wv, wo);

    dim3 gqkv(DM / 128, MROWS / 128, 3);
    gemm_qkv_kernel<<<gqkv, 256, G_SMEM>>>(q, k, v, wq, wk, wv, bq, bk, bv,
                                           qh, kh, vt);

    dim3 ga(S_LEN / 128, NB * NH);
    attn_mma_kernel<<<ga, 256, A_SMEM>>>(qh, kh, vt, at);

    dim3 gg(DM / 128, MROWS / 128);
    gemm_o_kernel<<<gg, 256, O_SMEM>>>(at, wo, bo, out);
}

// round 16
// speedup vs baseline: 1.0098x; 1.0098x over previous
#include <cuda_runtime.h>
#include <cuda_fp16.h>
#include <cstdint>

#define S_LEN 2048
#define NB 2
#define NH 16
#define DK 64
#define DM 1024
#define MROWS (NB * S_LEN)   // 4096
#define HEADELEMS ((size_t)NB * NH * S_LEN * DK)

// ---------------- scratch (__device__ globals; no allocs allowed) ----------
__device__ __half g_q[HEADELEMS];                        // [b,h][t][d], 1/8 folded
__device__ __half g_k[HEADELEMS];                        // [b,h][t][d]
__device__ __half g_vt[HEADELEMS];                       // [b,h][d][t]
__device__ __half g_at[(size_t)MROWS * DM];              // attention out [b][s][h*64+d]
__device__ __half g_wq[DM * DM], g_wk[DM * DM], g_wv[DM * DM], g_wo[DM * DM];

// ---------------- PTX helpers ----------------------------------------------
__device__ __forceinline__ uint32_t smem_u32(const void* p) {
    uint32_t a;
    asm("{ .reg .u64 t; cvta.to.shared.u64 t, %1; cvt.u32.u64 %0, t; }" : "=r"(a) : "l"(p));
    return a;
}
#define CP16(dst, src) asm volatile("cp.async.ca.shared.global [%0], [%1], 16;" :: "r"(dst), "l"(src))
#define CPCOMMIT()     asm volatile("cp.async.commit_group;" ::: "memory")
#define CPWAIT0()      asm volatile("cp.async.wait_group 0;" ::: "memory")

__device__ __forceinline__ void ldsm4(uint32_t* r, uint32_t a) {
    asm volatile("ldmatrix.sync.aligned.m8n8.x4.shared.b16 {%0,%1,%2,%3}, [%4];"
                 : "=r"(r[0]), "=r"(r[1]), "=r"(r[2]), "=r"(r[3]) : "r"(a));
}
__device__ __forceinline__ void mma16816(float* d, const uint32_t* a, const uint32_t* b) {
    asm volatile("mma.sync.aligned.m16n8k16.row.col.f32.f16.f16.f32 "
                 "{%0,%1,%2,%3},{%4,%5,%6,%7},{%8,%9},{%0,%1,%2,%3};"
                 : "+f"(d[0]), "+f"(d[1]), "+f"(d[2]), "+f"(d[3])
                 : "r"(a[0]), "r"(a[1]), "r"(a[2]), "r"(a[3]), "r"(b[0]), "r"(b[1]));
}

__device__ __forceinline__ uint32_t pack2(uint16_t a, uint16_t b) {
    return (uint32_t)a | ((uint32_t)b << 16);
}
__device__ __forceinline__ uint32_t pcvt2(float x, float y) {
    return pack2(__half_as_ushort(__float2half_rn(x)),
                 __half_as_ushort(__float2half_rn(y)));
}

// ---------------------------------------------------------------------------
// Fused weight transpose + convert (z selects which W):  T[n][k] = fp16(W[k][n])
// ---------------------------------------------------------------------------
__global__ __launch_bounds__(256) void wsplit_kernel(
    const float* __restrict__ W0, const float* __restrict__ W1,
    const float* __restrict__ W2, const float* __restrict__ W3,
    __half* __restrict__ T0, __half* __restrict__ T1,
    __half* __restrict__ T2, __half* __restrict__ T3)
{
    const int z = blockIdx.z;
    const float* W = (z == 0) ? W0 : (z == 1) ? W1 : (z == 2) ? W2 : W3;
    __half* Th     = (z == 0) ? T0 : (z == 1) ? T1 : (z == 2) ? T2 : T3;

    __shared__ float ts[32][33];
    const int tid = threadIdx.x;
    const int tx = tid & 31, ty = tid >> 5;
    const int k0 = blockIdx.x * 32, n0 = blockIdx.y * 32;
#pragma unroll
    for (int p = 0; p < 4; p++)
        ts[ty + 8 * p][tx] = W[(size_t)(k0 + ty + 8 * p) * DM + n0 + tx];
    __syncthreads();
#pragma unroll
    for (int p = 0; p < 4; p++) {
        const int r = ty + 8 * p;
        Th[(size_t)(n0 + r) * DM + k0 + tx] = __float2half_rn(ts[tx][r]);
    }
}

// ---------------------------------------------------------------------------
// Fused QKV GEMM: K macro-chunk 64 (4 k16 steps per sync), 144B-stride stages.
// A (fp32) staged in two 32-col register halves; A(ch+1) load overlaps wait.
// ---------------------------------------------------------------------------
#define Q_ST 18432              // stage: 128 rows x 144B
#define G_SMEM (4 * Q_ST)       // 73728 (also >= 128*136*2 V-bounce)
#define TPAD 136

__global__ __launch_bounds__(256, 2) void gemm_qkv_kernel(
    const float* __restrict__ A0, const float* __restrict__ A1,
    const float* __restrict__ A2,
    const __half* __restrict__ B0, const __half* __restrict__ B1,
    const __half* __restrict__ B2,
    const float* __restrict__ bias0, const float* __restrict__ bias1,
    const float* __restrict__ bias2,
    __half* __restrict__ O0, __half* __restrict__ O1, __half* __restrict__ O2)
{
    extern __shared__ char smc[];
    const uint32_t smb = smem_u32(smc);
    const int z = blockIdx.z;
    const float*  A    = (z == 0) ? A0 : (z == 1) ? A1 : A2;
    const __half* Bh   = (z == 0) ? B0 : (z == 1) ? B1 : B2;
    const float*  bias = (z == 0) ? bias0 : (z == 1) ? bias1 : bias2;
    __half* Oh         = (z == 0) ? O0 : (z == 1) ? O1 : O2;

    const int tid = threadIdx.x, lane = tid & 31, wid = tid >> 5;
    const int m0 = blockIdx.y * 128, n0 = blockIdx.x * 128;
    const int wm = (wid >> 2) * 64, wn = (wid & 3) * 32;
    const uint32_t SAH = smb, SBH = smb + 2 * Q_ST;

    const int r0a = tid >> 2, c0a = tid & 3;   // A loader: 64 rows x 4x8 fp32 cols

    // prologue: A chunk0 half0 -> regs; B chunk0 (64 k-cols) -> cp.async
    float4 areg[2][2];
#pragma unroll
    for (int p = 0; p < 2; p++) {
        const float* src = A + (size_t)(m0 + r0a + p * 64) * DM + c0a * 8;
        areg[p][0] = ((const float4*)src)[0];
        areg[p][1] = ((const float4*)src)[1];
    }
#pragma unroll
    for (int p = 0; p < 4; p++) {
        const int idx = tid + p * 256, r = idx >> 3, c = idx & 7;
        CP16(SBH + (uint32_t)r * 144u + (uint32_t)c * 16u,
             Bh + (size_t)(n0 + r) * DM + c * 8);
    }
    CPCOMMIT();

    float acc[4][4][4];
#pragma unroll
    for (int a = 0; a < 4; a++)
#pragma unroll
        for (int b = 0; b < 4; b++)
#pragma unroll
            for (int c = 0; c < 4; c++) acc[a][b][c] = 0.f;

    for (int ch = 0; ch < 16; ch++) {
        const uint32_t so = (uint32_t)(ch & 1) * Q_ST;
        // store A half0 (cols 0-31 of this macro-chunk)
#pragma unroll
        for (int p = 0; p < 2; p++) {
            uint4 v;
            v.x = pcvt2(areg[p][0].x, areg[p][0].y);
            v.y = pcvt2(areg[p][0].z, areg[p][0].w);
            v.z = pcvt2(areg[p][1].x, areg[p][1].y);
            v.w = pcvt2(areg[p][1].z, areg[p][1].w);
            *(uint4*)(smc + (uint32_t)(r0a + p * 64) * 144u +
                      (uint32_t)c0a * 16u + so) = v;
        }
        // load + store A half1 (cols 32-63)
        {
            const int k0 = ch * 64 + 32;
#pragma unroll
            for (int p = 0; p < 2; p++) {
                const float* src = A + (size_t)(m0 + r0a + p * 64) * DM + k0 + c0a * 8;
                areg[p][0] = ((const float4*)src)[0];
                areg[p][1] = ((const float4*)src)[1];
            }
#pragma unroll
            for (int p = 0; p < 2; p++) {
                uint4 v;
                v.x = pcvt2(areg[p][0].x, areg[p][0].y);
                v.y = pcvt2(areg[p][0].z, areg[p][0].w);
                v.z = pcvt2(areg[p][1].x, areg[p][1].y);
                v.w = pcvt2(areg[p][1].z, areg[p][1].w);
                *(uint4*)(smc + (uint32_t)(r0a + p * 64) * 144u + 64u +
                          (uint32_t)c0a * 16u + so) = v;
            }
        }
        // areg is dead now: issue A(ch+1) loads BEFORE the wait/barrier so the
        // LDGs overlap the cp.async drain + sync.
        if (ch + 1 < 16) {
            const int k0 = (ch + 1) * 64;
#pragma unroll
            for (int p = 0; p < 2; p++) {
                const float* src = A + (size_t)(m0 + r0a + p * 64) * DM + k0 + c0a * 8;
                areg[p][0] = ((const float4*)src)[0];
                areg[p][1] = ((const float4*)src)[1];
            }
        }
        CPWAIT0();
        __syncthreads();
        if (ch + 1 < 16) {
            const int k0 = (ch + 1) * 64;
            const uint32_t sn = (uint32_t)((ch + 1) & 1) * Q_ST;
#pragma unroll
            for (int p = 0; p < 4; p++) {
                const int idx = tid + p * 256, r = idx >> 3, c = idx & 7;
                CP16(SBH + (uint32_t)r * 144u + (uint32_t)c * 16u + sn,
                     Bh + (size_t)(n0 + r) * DM + k0 + c * 8);
            }
            CPCOMMIT();
        }
#pragma unroll
        for (int ks = 0; ks < 4; ks++) {
            uint32_t ah[4][4], bh[4][2];
            const uint32_t aoff = (uint32_t)((lane & 15) * 144 +
                                  (ks * 16 + (lane >> 4) * 8) * 2) + so;
#pragma unroll
            for (int mb = 0; mb < 4; mb++)
                ldsm4(ah[mb], SAH + (uint32_t)(wm + mb * 16) * 144u + aoff);
            const uint32_t boff = (uint32_t)(((lane >> 4) & 1) * 8 * 144 +
                                  (lane & 7) * 144 +
                                  (ks * 16 + ((lane >> 3) & 1) * 8) * 2) + so;
#pragma unroll
            for (int nbp = 0; nbp < 2; nbp++) {
                uint32_t t[4];
                ldsm4(t, SBH + (uint32_t)(wn + nbp * 16) * 144u + boff);
                bh[2 * nbp][0] = t[0];     bh[2 * nbp][1] = t[1];
                bh[2 * nbp + 1][0] = t[2]; bh[2 * nbp + 1][1] = t[3];
            }
#pragma unroll
            for (int mb = 0; mb < 4; mb++)
#pragma unroll
                for (int nb = 0; nb < 4; nb++)
                    mma16816(acc[mb][nb], ah[mb], bh[nb]);
        }
    }
    __syncthreads();

    const int lr = lane >> 2, lc = (lane & 3) * 2;
    if (z != 2) {
        const float sc = (z == 0) ? 0.125f : 1.0f;
#pragma unroll
        for (int mb = 0; mb < 4; mb++) {
#pragma unroll
            for (int nb = 0; nb < 4; nb++) {
                const int col = n0 + wn + nb * 8 + lc;
                const float b0 = bias[col], b1 = bias[col + 1];
#pragma unroll
                for (int half_ = 0; half_ < 2; half_++) {
                    const int row = m0 + wm + mb * 16 + lr + 8 * half_;
                    const float v0 = (acc[mb][nb][2 * half_] + b0) * sc;
                    const float v1 = (acc[mb][nb][2 * half_ + 1] + b1) * sc;
                    const int bb = row >> 11, ss = row & (S_LEN - 1);
                    const int h = col >> 6, d = col & 63;
                    const size_t base = (((size_t)(bb * NH + h) * S_LEN + ss) << 6) + d;
                    *(uint32_t*)(Oh + base) = pcvt2(v0, v1);
                }
            }
        }
    } else {
        __half* tsm = (__half*)smc;
#pragma unroll
        for (int mb = 0; mb < 4; mb++) {
#pragma unroll
            for (int nb = 0; nb < 4; nb++) {
                const int col = wn + nb * 8 + lc;
                const float b0 = bias[n0 + col], b1 = bias[n0 + col + 1];
#pragma unroll
                for (int half_ = 0; half_ < 2; half_++) {
                    const int row = wm + mb * 16 + lr + 8 * half_;
                    tsm[(size_t)col * TPAD + row] =
                        __float2half_rn(acc[mb][nb][2 * half_] + b0);
                    tsm[(size_t)(col + 1) * TPAD + row] =
                        __float2half_rn(acc[mb][nb][2 * half_ + 1] + b1);
                }
            }
        }
        __syncthreads();
        const int dl = tid >> 1;
        const int tof = (tid & 1) * 64;
        const int bb = m0 >> 11, ss0 = (m0 & (S_LEN - 1)) + tof;
        const int n = n0 + dl, h = n >> 6, d = n & 63;
        __half* dst = Oh + ((size_t)(bb * NH + h) * DK + d) * S_LEN + ss0;
        const __half* srcr = tsm + (size_t)dl * TPAD + tof;
#pragma unroll
        for (int j = 0; j < 8; j++)
            ((uint4*)dst)[j] = ((const uint4*)srcr)[j];
    }
}

// ---------------------------------------------------------------------------
// Output projection GEMM: macro-chunk 64, 144B rows.
// ---------------------------------------------------------------------------
#define O_ST 18432
#define O_SMEM (4 * O_ST)

__global__ __launch_bounds__(256, 2) void gemm_o_kernel(
    const __half* __restrict__ Ah, const __half* __restrict__ Bh,
    const float* __restrict__ bias, float* __restrict__ Of)
{
    extern __shared__ char smc[];
    const uint32_t smb = smem_u32(smc);
    const int tid = threadIdx.x, lane = tid & 31, wid = tid >> 5;
    const int m0 = blockIdx.y * 128, n0 = blockIdx.x * 128;
    const int wm = (wid >> 2) * 64, wn = (wid & 3) * 32;
    const uint32_t SAH = smb, SBH = smb + 2 * O_ST;

#pragma unroll
    for (int p = 0; p < 4; p++) {
        const int idx = tid + p * 256, r = idx >> 3, c = idx & 7;
        const uint32_t d = (uint32_t)r * 144u + (uint32_t)c * 16u;
        CP16(SAH + d, Ah + (size_t)(m0 + r) * DM + c * 8);
        CP16(SBH + d, Bh + (size_t)(n0 + r) * DM + c * 8);
    }
    CPCOMMIT();

    float acc[4][4][4];
#pragma unroll
    for (int a = 0; a < 4; a++)
#pragma unroll
        for (int b = 0; b < 4; b++)
#pragma unroll
            for (int c = 0; c < 4; c++) acc[a][b][c] = 0.f;

    CPWAIT0();
    __syncthreads();

    for (int ch = 0; ch < 16; ch++) {
        if (ch > 0) { CPWAIT0(); __syncthreads(); }
        if (ch + 1 < 16) {
            const int k0 = (ch + 1) * 64;
            const uint32_t sn = (uint32_t)((ch + 1) & 1) * O_ST;
#pragma unroll
            for (int p = 0; p < 4; p++) {
                const int idx = tid + p * 256, r = idx >> 3, c = idx & 7;
                const uint32_t d = (uint32_t)r * 144u + (uint32_t)c * 16u + sn;
                CP16(SAH + d, Ah + (size_t)(m0 + r) * DM + k0 + c * 8);
                CP16(SBH + d, Bh + (size_t)(n0 + r) * DM + k0 + c * 8);
            }
            CPCOMMIT();
        }
        const uint32_t so = (uint32_t)(ch & 1) * O_ST;
#pragma unroll
        for (int ks = 0; ks < 4; ks++) {
            uint32_t ah[4][4], bh[4][2];
            const uint32_t aoff = (uint32_t)((lane & 15) * 144 +
                                  (ks * 16 + (lane >> 4) * 8) * 2) + so;
#pragma unroll
            for (int mb = 0; mb < 4; mb++)
                ldsm4(ah[mb], SAH + (uint32_t)(wm + mb * 16) * 144u + aoff);
            const uint32_t boff = (uint32_t)(((lane >> 4) & 1) * 8 * 144 +
                                  (lane & 7) * 144 +
                                  (ks * 16 + ((lane >> 3) & 1) * 8) * 2) + so;
#pragma unroll
            for (int nbp = 0; nbp < 2; nbp++) {
                uint32_t t[4];
                ldsm4(t, SBH + (uint32_t)(wn + nbp * 16) * 144u + boff);
                bh[2 * nbp][0] = t[0];     bh[2 * nbp][1] = t[1];
                bh[2 * nbp + 1][0] = t[2]; bh[2 * nbp + 1][1] = t[3];
            }
#pragma unroll
            for (int mb = 0; mb < 4; mb++)
#pragma unroll
                for (int nb = 0; nb < 4; nb++)
                    mma16816(acc[mb][nb], ah[mb], bh[nb]);
        }
    }

    const int lr = lane >> 2, lc = (lane & 3) * 2;
#pragma unroll
    for (int mb = 0; mb < 4; mb++) {
#pragma unroll
        for (int nb = 0; nb < 4; nb++) {
            const int col = n0 + wn + nb * 8 + lc;
            const float b0 = bias[col], b1 = bias[col + 1];
#pragma unroll
            for (int half_ = 0; half_ < 2; half_++) {
                const int row = m0 + wm + mb * 16 + lr + 8 * half_;
                *(float2*)(Of + (size_t)row * DM + col) =
                    make_float2(acc[mb][nb][2 * half_] + b0,
                                acc[mb][nb][2 * half_ + 1] + b1);
            }
        }
    }
}

// ---------------------------------------------------------------------------
// Flash attention: KV macro-chunk 128, Q frags hoisted.
// ---------------------------------------------------------------------------
#define AK_ST 18432
#define AV_ST 17408
#define A_QB  18432
#define A_SMEM (A_QB + 2 * AK_ST + 2 * AV_ST)

__global__ __launch_bounds__(256, 2) void attn_mma_kernel(
    const __half* __restrict__ Qh, const __half* __restrict__ Kh,
    const __half* __restrict__ Vth, __half* __restrict__ AO)
{
    extern __shared__ char smc[];
    const uint32_t smb = smem_u32(smc);
    const int tid = threadIdx.x, lane = tid & 31, wid = tid >> 5;
    const int bh = blockIdx.y;
    const int q0 = blockIdx.x * 128;
    const uint32_t SQH = smb;
    const uint32_t SKH = smb + A_QB, SVH = SKH + 2 * AK_ST;

    const size_t qbase = ((size_t)bh * S_LEN + q0) * DK;
    const size_t kbase = (size_t)bh * S_LEN * DK;
    const size_t vbase = (size_t)bh * DK * S_LEN;

    {
#pragma unroll
        for (int p = 0; p < 4; p++) {
            const int idx = tid + p * 256, r = idx >> 3, c = idx & 7;
            CP16(SQH + (uint32_t)r * 144u + (uint32_t)c * 16u,
                 Qh + qbase + (size_t)r * DK + c * 8);
            CP16(SKH + (uint32_t)r * 144u + (uint32_t)c * 16u,
                 Kh + kbase + (size_t)r * DK + c * 8);
        }
#pragma unroll
        for (int p = 0; p < 4; p++) {
            const int idx = tid + p * 256, r = idx >> 4, c = idx & 15;
            CP16(SVH + (uint32_t)r * 272u + (uint32_t)c * 16u,
                 Vth + vbase + (size_t)r * S_LEN + c * 8);
        }
        CPCOMMIT();
    }

    const int r0 = wid * 16;
    float oacc[8][4];
    float lsum[2] = {0.f, 0.f};
#pragma unroll
    for (int db = 0; db < 8; db++)
#pragma unroll
        for (int e = 0; e < 4; e++) oacc[db][e] = 0.f;

    CPWAIT0();
    __syncthreads();

    uint32_t qf_all[4][4];
#pragma unroll
    for (int ks = 0; ks < 4; ks++)
        ldsm4(qf_all[ks], SQH + (uint32_t)((r0 + (lane & 15)) * 144 +
                                           (ks * 16 + (lane >> 4) * 8) * 2));

    for (int i = 0; i < 16; i++) {
        if (i > 0) { CPWAIT0(); __syncthreads(); }
        if (i + 1 < 16) {
            const int t0 = (i + 1) * 128;
            const uint32_t skn = (uint32_t)((i + 1) & 1) * AK_ST;
            const uint32_t svn = (uint32_t)((i + 1) & 1) * AV_ST;
#pragma unroll
            for (int p = 0; p < 4; p++) {
                const int idx = tid + p * 256, r = idx >> 3, c = idx & 7;
                CP16(SKH + (uint32_t)r * 144u + (uint32_t)c * 16u + skn,
                     Kh + kbase + (size_t)(t0 + r) * DK + c * 8);
            }
#pragma unroll
            for (int p = 0; p < 4; p++) {
                const int idx = tid + p * 256, r = idx >> 4, c = idx & 15;
                CP16(SVH + (uint32_t)r * 272u + (uint32_t)c * 16u + svn,
                     Vth + vbase + (size_t)r * S_LEN + t0 + c * 8);
            }
            CPCOMMIT();
        }
        const uint32_t sk = (uint32_t)(i & 1) * AK_ST;
        const uint32_t sv = (uint32_t)(i & 1) * AV_ST;

#pragma unroll
        for (int hf = 0; hf < 2; hf++) {
            float sacc[8][4];
#pragma unroll
            for (int nb = 0; nb < 8; nb++)
#pragma unroll
                for (int e = 0; e < 4; e++) sacc[nb][e] = 0.f;
            const uint32_t kbs = SKH + sk + (uint32_t)(hf * 64) * 144u;
#pragma unroll
            for (int ks = 0; ks < 4; ks++) {
                const uint32_t bo = (uint32_t)(((lane >> 4) & 1) * 8 * 144 +
                                     (lane & 7) * 144 +
                                     (ks * 16 + ((lane >> 3) & 1) * 8) * 2);
#pragma unroll
                for (int nbp = 0; nbp < 4; nbp++) {
                    uint32_t t[4];
                    ldsm4(t, kbs + (uint32_t)(nbp * 16) * 144u + bo);
                    mma16816(sacc[2 * nbp],     qf_all[ks], t);
                    mma16816(sacc[2 * nbp + 1], qf_all[ks], t + 2);
                }
            }

#pragma unroll
            for (int nb = 0; nb < 8; nb++)
#pragma unroll
                for (int e = 0; e < 4; e++) {
                    const float p = __expf(sacc[nb][e]);
                    lsum[e >> 1] += p;
                    sacc[nb][e] = p;
                }

            const uint32_t vbs = SVH + sv;
#pragma unroll
            for (int ts = 0; ts < 4; ts++) {
                uint32_t ph[4];
                ph[0] = pcvt2(sacc[2 * ts][0],     sacc[2 * ts][1]);
                ph[1] = pcvt2(sacc[2 * ts][2],     sacc[2 * ts][3]);
                ph[2] = pcvt2(sacc[2 * ts + 1][0], sacc[2 * ts + 1][1]);
                ph[3] = pcvt2(sacc[2 * ts + 1][2], sacc[2 * ts + 1][3]);
                const uint32_t vo = (uint32_t)(((lane >> 4) & 1) * 8 * 272 +
                                     (lane & 7) * 272 +
                                     (hf * 64 + ts * 16 + ((lane >> 3) & 1) * 8) * 2);
#pragma unroll
                for (int dbp = 0; dbp < 4; dbp++) {
                    uint32_t t[4];
                    ldsm4(t, vbs + (uint32_t)(dbp * 16) * 272u + vo);
                    mma16816(oacc[2 * dbp],     ph, t);
                    mma16816(oacc[2 * dbp + 1], ph, t + 2);
                }
            }
        }
    }

#pragma unroll
    for (int e = 0; e < 2; e++) {
        lsum[e] += __shfl_xor_sync(0xffffffffu, lsum[e], 1);
        lsum[e] += __shfl_xor_sync(0xffffffffu, lsum[e], 2);
    }
    const float inv0 = 1.f / lsum[0], inv1 = 1.f / lsum[1];

    const int bb = bh >> 4, hh = bh & 15;
    const int rowa = q0 + r0 + (lane >> 2);
#pragma unroll
    for (int db = 0; db < 8; db++) {
        const int col = hh * 64 + db * 8 + (lane & 3) * 2;
        const size_t ba = ((size_t)bb * S_LEN + rowa) * DM + col;
        const size_t bb2 = ba + (size_t)8 * DM;
        *(uint32_t*)(AO + ba)  = pcvt2(oacc[db][0] * inv0, oacc[db][1] * inv0);
        *(uint32_t*)(AO + bb2) = pcvt2(oacc[db][2] * inv1, oacc[db][3] * inv1);
    }
}

// ---------------------------------------------------------------------------
extern "C" void kernel_launch(void* const* d_in, const int* in_sizes, int n_in,
                              void* d_out, int out_size)
{
    const float* q  = (const float*)d_in[0];
    const float* k  = (const float*)d_in[1];
    const float* v  = (const float*)d_in[2];
    const float* Wq = (const float*)d_in[3];
    const float* bq = (const float*)d_in[4];
    const float* Wk = (const float*)d_in[5];
    const float* bk = (const float*)d_in[6];
    const float* Wv = (const float*)d_in[7];
    const float* bv = (const float*)d_in[8];
    const float* Wo = (const float*)d_in[9];
    const float* bo = (const float*)d_in[10];
    float* out = (float*)d_out;

    __half *qh, *kh, *vt, *at, *wq, *wk, *wv, *wo;
    cudaGetSymbolAddress((void**)&qh, g_q);
    cudaGetSymbolAddress((void**)&kh, g_k);
    cudaGetSymbolAddress((void**)&vt, g_vt);
    cudaGetSymbolAddress((void**)&at, g_at);
    cudaGetSymbolAddress((void**)&wq, g_wq);
    cudaGetSymbolAddress((void**)&wk, g_wk);
    cudaGetSymbolAddress((void**)&wv, g_wv);
    cudaGetSymbolAddress((void**)&wo, g_wo);

    cudaFuncSetAttribute(gemm_qkv_kernel, cudaFuncAttributeMaxDynamicSharedMemorySize, G_SMEM);
    cudaFuncSetAttribute(gemm_o_kernel, cudaFuncAttributeMaxDynamicSharedMemorySize, O_SMEM);
    cudaFuncSetAttribute(attn_mma_kernel, cudaFuncAttributeMaxDynamicSharedMemorySize, A_SMEM);

    dim3 wg(32, 32, 4);
    wsplit_kernel<<<wg, 256>>>(Wq, Wk, Wv, Wo, wq, wk, wv, wo);

    dim3 gqkv(DM / 128, MROWS / 128, 3);
    gemm_qkv_kernel<<<gqkv, 256, G_SMEM>>>(q, k, v, wq, wk, wv, bq, bk, bv,
                                           qh, kh, vt);

    dim3 ga(S_LEN / 128, NB * NH);
    attn_mma_kernel<<<ga, 256, A_SMEM>>>(qh, kh, vt, at);

    dim3 gg(DM / 128, MROWS / 128);
    gemm_o_kernel<<<gg, 256, O_SMEM>>>(at, wo, bo, out);
}